// round 4
// baseline (speedup 1.0000x reference)
#include <cuda_runtime.h>
#include <math_constants.h>

// Spatial-grid exact L-inf nearest neighbor.
// Grid: G x G cells over [X0, X0+EXT]^2. Points binned via CSR (prefix sum),
// so each row of cells is a contiguous span of points -> ring scans touch
// one span per row. Expanding-ring search with the contraction-safe bound:
// after scanning rings 0..r-1, all unscanned points have d >= (r-1)*H.

#define G      128
#define NCELL  (G * G)
#define X0     (-4.5f)
#define EXT    9.0f
#define H      (EXT / (float)G)          // 0.0703125, binary exact
#define INVH   ((float)G / EXT)
#define MAXPTS 16384

__device__ int    g_cnt[NCELL];          // counts, then scatter cursors
__device__ int    g_off[NCELL + 1];      // CSR offsets
__device__ float4 g_pts[MAXPTS];         // (x, y, idx_bits, unused)

__device__ __forceinline__ int cell_coord(float v) {
    int c = __float2int_rd((v - X0) * INVH);
    return min(max(c, 0), G - 1);
}

__global__ void zero_k() {
    int i = blockIdx.x * blockDim.x + threadIdx.x;
    if (i < NCELL) g_cnt[i] = 0;
}

__global__ void count_k(const float* __restrict__ B, int N) {
    int n = blockIdx.x * blockDim.x + threadIdx.x;
    if (n >= N) return;
    int cx = cell_coord(B[n]);
    int cy = cell_coord(B[N + n]);
    atomicAdd(&g_cnt[cy * G + cx], 1);
}

__global__ void scan_k() {                // single block, 1024 threads
    __shared__ int sh[1024];
    int t = threadIdx.x;
    int base = t * (NCELL / 1024);        // 16 cells per thread
    int local[NCELL / 1024];
    int s = 0;
    #pragma unroll
    for (int i = 0; i < NCELL / 1024; ++i) { local[i] = g_cnt[base + i]; s += local[i]; }
    sh[t] = s;
    __syncthreads();
    for (int off = 1; off < 1024; off <<= 1) {
        int v = (t >= off) ? sh[t - off] : 0;
        __syncthreads();
        sh[t] += v;
        __syncthreads();
    }
    int excl = sh[t] - s;
    #pragma unroll
    for (int i = 0; i < NCELL / 1024; ++i) {
        g_off[base + i] = excl;
        excl += local[i];
        g_cnt[base + i] = 0;              // reset for scatter cursors
    }
    if (t == 1023) g_off[NCELL] = excl;
}

__global__ void scatter_k(const float* __restrict__ B, int N) {
    int n = blockIdx.x * blockDim.x + threadIdx.x;
    if (n >= N) return;
    float x = B[n], y = B[N + n];
    int c = cell_coord(y) * G + cell_coord(x);
    int pos = g_off[c] + atomicAdd(&g_cnt[c], 1);
    g_pts[pos] = make_float4(x, y, __int_as_float(n), 0.0f);
}

struct Best { float d, dx, dy; int idx; };

__device__ __forceinline__ void scan_span(int s, int e, float ax, float ay, Best& b) {
    for (int p = s; p < e; ++p) {
        float4 pt = g_pts[p];
        float dx = ax - pt.x;
        float dy = ay - pt.y;
        float d  = fmaxf(fabsf(dx), fabsf(dy));
        int  idx = __float_as_int(pt.z);
        bool take = (d < b.d) || (d == b.d && idx < b.idx);
        if (take) { b.d = d; b.dx = dx; b.dy = dy; b.idx = idx; }
    }
}

__global__ void __launch_bounds__(128)
query_k(const float* __restrict__ A, float* __restrict__ out, int Q) {
    int q = blockIdx.x * blockDim.x + threadIdx.x;
    if (q >= Q) return;
    float ax = A[2 * q];
    float ay = A[2 * q + 1];
    int cx = cell_coord(ax);
    int cy = cell_coord(ay);

    Best b;
    b.d = CUDART_INF_F; b.dx = 0.0f; b.dy = 0.0f; b.idx = 0x7fffffff;

    for (int r = 0; r < G; ++r) {
        // Unscanned points lie in rings >= r  ->  d >= (r-1)*H.
        if (r >= 1 && b.d <= (float)(r - 1) * H) break;

        int ilo = max(cx - r, 0), ihi = min(cx + r, G - 1);
        int jlo = cy - r,        jhi = cy + r;

        if (jlo >= 0) {                   // top row (also the r=0 cell)
            int base = jlo * G;
            scan_span(g_off[base + ilo], g_off[base + ihi + 1], ax, ay, b);
        }
        if (r > 0 && jhi <= G - 1) {      // bottom row
            int base = jhi * G;
            scan_span(g_off[base + ilo], g_off[base + ihi + 1], ax, ay, b);
        }
        if (r > 0) {                      // side columns, one cell per row
            int jm0 = max(jlo + 1, 0), jm1 = min(jhi - 1, G - 1);
            int il = cx - r, ir = cx + r;
            for (int j = jm0; j <= jm1; ++j) {
                int base = j * G;
                if (il >= 0)     scan_span(g_off[base + il], g_off[base + il + 1], ax, ay, b);
                if (ir <= G - 1) scan_span(g_off[base + ir], g_off[base + ir + 1], ax, ay, b);
            }
        }
        // Entire grid covered -> nothing left to scan.
        if (ilo == 0 && ihi == G - 1 && jlo <= 0 && jhi >= G - 1) break;
    }

    ((float2*)out)[q] = make_float2(b.dx, b.dy);
}

extern "C" void kernel_launch(void* const* d_in, const int* in_sizes, int n_in,
                              void* d_out, int out_size)
{
    const float* A = (const float*)d_in[0];   // [Q, 2]
    const float* B = (const float*)d_in[1];   // [2, N]
    float*     out = (float*)d_out;           // [Q, 2]

    const int Q = in_sizes[0] / 2;
    const int N = in_sizes[1] / 2;

    zero_k   <<<(NCELL + 255) / 256, 256>>>();
    count_k  <<<(N + 255) / 256, 256>>>(B, N);
    scan_k   <<<1, 1024>>>();
    scatter_k<<<(N + 255) / 256, 256>>>(B, N);
    query_k  <<<(Q + 127) / 128, 128>>>(A, out, Q);
}

// round 5
// speedup vs baseline: 3.8217x; 3.8217x over previous
#include <cuda_runtime.h>
#include <math_constants.h>

// Exact L-inf nearest neighbor via spatial grid, 2 kernels total:
//   build_k : ONE block bins all of B into a CSR grid (smem count/scan/scatter).
//   query_k : 16 lanes per query; expanding Chebyshev rings, cell-per-lane,
//             shfl lexicographic (dist, idx) reduce -> exact argmin semantics.
// Bound (contraction-safe even with clamped cells): after rings 0..r-1 are
// fully scanned, every unscanned point has d >= (r-1)*H.

#define G      64
#define NCELL  (G * G)
#define X0     (-4.5f)
#define EXT    9.0f
#define H      (EXT / (float)G)          // 0.140625, binary exact
#define INVH   ((float)G / EXT)
#define MAXPTS 16384

__device__ int    g_off[NCELL + 1];      // CSR offsets
__device__ float4 g_pts[MAXPTS];         // (x, y, idx_bits, 0)

__device__ __forceinline__ int cell_coord(float v) {
    int c = __float2int_rd((v - X0) * INVH);
    return min(max(c, 0), G - 1);
}

// ---------------- build: one block does everything ----------------
__global__ void __launch_bounds__(1024)
build_k(const float* __restrict__ B, int N)
{
    __shared__ int s_cnt[NCELL];
    __shared__ int s_off[NCELL];
    __shared__ int s_wsum[32];

    const int t = threadIdx.x;
    for (int c = t; c < NCELL; c += 1024) s_cnt[c] = 0;
    __syncthreads();

    for (int n = t; n < N; n += 1024) {
        int cx = cell_coord(B[n]);
        int cy = cell_coord(B[N + n]);
        atomicAdd(&s_cnt[cy * G + cx], 1);
    }
    __syncthreads();

    // exclusive scan of 4096 cells: 4 per thread + block scan
    const int base = t * (NCELL / 1024);
    int l0 = s_cnt[base + 0], l1 = s_cnt[base + 1];
    int l2 = s_cnt[base + 2], l3 = s_cnt[base + 3];
    int tot = l0 + l1 + l2 + l3;

    const int lane = t & 31, wid = t >> 5;
    int v = tot;
    #pragma unroll
    for (int m = 1; m < 32; m <<= 1) {
        int u = __shfl_up_sync(0xffffffffu, v, m);
        if (lane >= m) v += u;
    }
    if (lane == 31) s_wsum[wid] = v;
    __syncthreads();
    if (wid == 0) {
        int w = s_wsum[lane];
        #pragma unroll
        for (int m = 1; m < 32; m <<= 1) {
            int u = __shfl_up_sync(0xffffffffu, w, m);
            if (lane >= m) w += u;
        }
        s_wsum[lane] = w;
    }
    __syncthreads();

    int excl = v - tot + (wid ? s_wsum[wid - 1] : 0);
    s_off[base + 0] = excl;
    s_off[base + 1] = excl + l0;
    s_off[base + 2] = excl + l0 + l1;
    s_off[base + 3] = excl + l0 + l1 + l2;
    s_cnt[base + 0] = 0; s_cnt[base + 1] = 0;
    s_cnt[base + 2] = 0; s_cnt[base + 3] = 0;
    __syncthreads();

    for (int c = t; c < NCELL; c += 1024) g_off[c] = s_off[c];
    if (t == 1023) g_off[NCELL] = excl + tot;   // == N

    // scatter (cursor in smem; order nondeterministic, output isn't: ties by idx)
    for (int n = t; n < N; n += 1024) {
        float x = B[n], y = B[N + n];
        int c = cell_coord(y) * G + cell_coord(x);
        int pos = s_off[c] + atomicAdd(&s_cnt[c], 1);
        g_pts[pos] = make_float4(x, y, __int_as_float(n), 0.0f);
    }
}

// ---------------- query: 16 lanes per query ----------------
__device__ __forceinline__ void scan_cell(int c, float ax, float ay,
                                          float& best, unsigned& bpay)
{
    int s = __ldg(&g_off[c]);
    int e = __ldg(&g_off[c + 1]);
    for (int p = s; p < e; ++p) {
        float4 pt = __ldg(&g_pts[p]);
        float dx = ax - pt.x;
        float dy = ay - pt.y;
        float d  = fmaxf(fabsf(dx), fabsf(dy));
        unsigned pay = (((unsigned)__float_as_uint(pt.z)) << 16) | (unsigned)p;
        bool take = (d < best) || (d == best && pay < bpay);
        best = take ? d   : best;
        bpay = take ? pay : bpay;
    }
}

__global__ void __launch_bounds__(256)
query_k(const float* __restrict__ A, float* __restrict__ out, int Q)
{
    const int tid  = blockIdx.x * 256 + threadIdx.x;
    const int q    = tid >> 4;
    const int lane = tid & 15;
    if (q >= Q) return;

    const unsigned gmask = 0xFFFFu << (threadIdx.x & 16);  // own 16-lane group

    const float ax = __ldg(&A[2 * q]);
    const float ay = __ldg(&A[2 * q + 1]);
    const int cx = cell_coord(ax);
    const int cy = cell_coord(ay);

    float    best = CUDART_INF_F;
    unsigned bpay = 0xFFFFFFFFu;

    // rings 0 + 1: 9 cells, one per lane
    if (lane < 9) {
        int di = lane % 3 - 1;
        int dj = lane / 3 - 1;
        int i = cx + di, j = cy + dj;
        if ((unsigned)i < G && (unsigned)j < G)
            scan_cell(j * G + i, ax, ay, best, bpay);
    }
    #pragma unroll
    for (int m = 8; m >= 1; m >>= 1) {
        float    od = __shfl_xor_sync(gmask, best, m);
        unsigned op = __shfl_xor_sync(gmask, bpay, m);
        bool take = (od < best) || (od == best && op < bpay);
        best = take ? od : best;
        bpay = take ? op : bpay;
    }

    for (int r = 2; ; ++r) {
        // unscanned points are in rings >= r  ->  d >= (r-1)*H
        if (best + 1e-5f < (float)(r - 1) * H) break;
        // rings 0..r-1 already cover the whole grid -> nothing left
        if (cx - (r - 1) <= 0 && cx + (r - 1) >= G - 1 &&
            cy - (r - 1) <= 0 && cy + (r - 1) >= G - 1) break;

        int nc = 8 * r;
        for (int tc = lane; tc < nc; tc += 16) {
            int i, j;
            if (tc < 2 * r + 1)          { i = cx - r + tc;               j = cy - r; }
            else if (tc < 4 * r + 2)     { i = cx - r + (tc - (2*r + 1)); j = cy + r; }
            else { int s = tc - (4*r + 2); j = cy - r + 1 + (s >> 1);
                   i = (s & 1) ? cx + r : cx - r; }
            if ((unsigned)i < G && (unsigned)j < G)
                scan_cell(j * G + i, ax, ay, best, bpay);
        }
        #pragma unroll
        for (int m = 8; m >= 1; m >>= 1) {
            float    od = __shfl_xor_sync(gmask, best, m);
            unsigned op = __shfl_xor_sync(gmask, bpay, m);
            bool take = (od < best) || (od == best && op < bpay);
            best = take ? od : best;
            bpay = take ? op : bpay;
        }
    }

    if (lane == 0) {
        int pos = (int)(bpay & 0xFFFFu);
        float4 pt = __ldg(&g_pts[pos]);
        ((float2*)out)[q] = make_float2(ax - pt.x, ay - pt.y);
    }
}

extern "C" void kernel_launch(void* const* d_in, const int* in_sizes, int n_in,
                              void* d_out, int out_size)
{
    const float* A = (const float*)d_in[0];   // [Q, 2]
    const float* B = (const float*)d_in[1];   // [2, N]
    float*     out = (float*)d_out;           // [Q, 2]

    const int Q = in_sizes[0] / 2;
    const int N = in_sizes[1] / 2;

    build_k<<<1, 1024>>>(B, N);

    const int total  = Q * 16;
    const int blocks = (total + 255) / 256;
    query_k<<<blocks, 256>>>(A, out, Q);
}

// round 6
// speedup vs baseline: 3.8266x; 1.0013x over previous
#include <cuda_runtime.h>
#include <math_constants.h>

// Exact L-inf nearest neighbor via spatial CSR grid.
//   build_k : ONE block bins B (count/scan/scatter in smem).
//   query_k : 8 lanes/query. Fast path scans rings 0+1 as 3 contiguous row
//             spans with POINTS distributed across lanes; fallback expanding
//             rings. State packed as u64 (dist_bits<<32 | idx<<16 | pos) so
//             min() IS the lexicographic (d, idx) argmin -> exact semantics.
// Bound (contraction-safe under cell clamping): once rings 0..r-1 are fully
// scanned, every unscanned point has d >= (r-1)*H.

#define G      64
#define NCELL  (G * G)
#define X0     (-4.5f)
#define EXT    9.0f
#define H      (EXT / (float)G)          // 0.140625, binary exact
#define INVH   ((float)G / EXT)
#define MAXPTS 16384
#define LPQ    8                         // lanes per query

__device__ int    g_off[NCELL + 1];
__device__ float4 g_pts[MAXPTS];         // (x, y, idx_bits, 0)

__device__ __forceinline__ int cell_coord(float v) {
    int c = __float2int_rd((v - X0) * INVH);
    return min(max(c, 0), G - 1);
}

// ---------------- build: one block ----------------
__global__ void __launch_bounds__(1024)
build_k(const float* __restrict__ B, int N)
{
    __shared__ int s_cnt[NCELL];
    __shared__ int s_off[NCELL];
    __shared__ int s_wsum[32];

    const int t = threadIdx.x;
    for (int c = t; c < NCELL; c += 1024) s_cnt[c] = 0;
    __syncthreads();

    // load this thread's points once; reuse for scatter
    float px[4], py[4]; int pc[4]; int np = 0;
    for (int n = t; n < N; n += 1024) {
        float x = B[n], y = B[N + n];
        int c = cell_coord(y) * G + cell_coord(x);
        px[np] = x; py[np] = y; pc[np] = (c << 12) | (n & 0xFFF); ++np;
        atomicAdd(&s_cnt[c], 1);
    }
    __syncthreads();

    const int base = t * (NCELL / 1024);
    int l0 = s_cnt[base + 0], l1 = s_cnt[base + 1];
    int l2 = s_cnt[base + 2], l3 = s_cnt[base + 3];
    int tot = l0 + l1 + l2 + l3;

    const int lane = t & 31, wid = t >> 5;
    int v = tot;
    #pragma unroll
    for (int m = 1; m < 32; m <<= 1) {
        int u = __shfl_up_sync(0xffffffffu, v, m);
        if (lane >= m) v += u;
    }
    if (lane == 31) s_wsum[wid] = v;
    __syncthreads();
    if (wid == 0) {
        int w = s_wsum[lane];
        #pragma unroll
        for (int m = 1; m < 32; m <<= 1) {
            int u = __shfl_up_sync(0xffffffffu, w, m);
            if (lane >= m) w += u;
        }
        s_wsum[lane] = w;
    }
    __syncthreads();

    int excl = v - tot + (wid ? s_wsum[wid - 1] : 0);
    s_off[base + 0] = excl;
    s_off[base + 1] = excl + l0;
    s_off[base + 2] = excl + l0 + l1;
    s_off[base + 3] = excl + l0 + l1 + l2;
    s_cnt[base + 0] = 0; s_cnt[base + 1] = 0;
    s_cnt[base + 2] = 0; s_cnt[base + 3] = 0;
    __syncthreads();

    for (int c = t; c < NCELL; c += 1024) g_off[c] = s_off[c];
    if (t == 1023) g_off[NCELL] = excl + tot;

    for (int k = 0; k < np; ++k) {
        int c = pc[k] >> 12;
        int n = ((t & ~1023) ? 0 : 0) + ( (pc[k] & 0xFFF) | (0) );  // n reconstructed below
        // reconstruct full n: points were strided n = t + 1024*k
        n = t + (k << 10);
        int pos = s_off[c] + atomicAdd(&s_cnt[c], 1);
        g_pts[pos] = make_float4(px[k], py[k], __int_as_float(n), 0.0f);
    }
}

// ---------------- query ----------------
__device__ __forceinline__ unsigned long long
cand_pack(float d, int idx, int pos) {
    unsigned pay = (((unsigned)idx) << 16) | (unsigned)pos;
    return (((unsigned long long)__float_as_uint(d)) << 32) | pay;
}

__device__ __forceinline__ void scan_point(int p, float ax, float ay,
                                           unsigned long long& best)
{
    float4 pt = __ldg(&g_pts[p]);
    float dx = ax - pt.x;
    float dy = ay - pt.y;
    float d  = fmaxf(fabsf(dx), fabsf(dy));
    unsigned long long c = cand_pack(d, __float_as_int(pt.z), p);
    best = min(best, c);
}

__device__ __forceinline__ void scan_cell(int c, float ax, float ay,
                                          unsigned long long& best)
{
    int s = __ldg(&g_off[c]);
    int e = __ldg(&g_off[c + 1]);
    for (int p = s; p < e; ++p) scan_point(p, ax, ay, best);
}

__global__ void __launch_bounds__(256)
query_k(const float* __restrict__ A, float* __restrict__ out, int Q)
{
    const int tid  = blockIdx.x * 256 + threadIdx.x;
    const int q    = tid / LPQ;
    const int lane = tid & (LPQ - 1);
    if (q >= Q) return;

    const unsigned gmask = 0xFFu << (threadIdx.x & 24);

    const float ax = __ldg(&A[2 * q]);
    const float ay = __ldg(&A[2 * q + 1]);
    const int cx = cell_coord(ax);
    const int cy = cell_coord(ay);

    unsigned long long best = 0xFFFFFFFFFFFFFFFFull;

    // ---- fast path: rings 0+1 = 3 row spans, points spread across lanes ----
    {
        const int i0  = max(cx - 1, 0);
        const int i1p = min(cx + 1, G - 1) + 1;

        int s0 = 0, c0 = 0, s1, c1, s2 = 0, c2 = 0;
        if (cy - 1 >= 0) {
            int rb = (cy - 1) * G;
            s0 = __ldg(&g_off[rb + i0]); c0 = __ldg(&g_off[rb + i1p]) - s0;
        }
        {
            int rb = cy * G;
            s1 = __ldg(&g_off[rb + i0]); c1 = __ldg(&g_off[rb + i1p]) - s1;
        }
        if (cy + 1 <= G - 1) {
            int rb = (cy + 1) * G;
            s2 = __ldg(&g_off[rb + i0]); c2 = __ldg(&g_off[rb + i1p]) - s2;
        }

        const int T = c0 + c1 + c2;
        for (int k = lane; k < T; k += LPQ) {
            int p;
            if (k < c0)           p = s0 + k;
            else if (k < c0 + c1) p = s1 + (k - c0);
            else                  p = s2 + (k - c0 - c1);
            scan_point(p, ax, ay, best);
        }
    }
    #pragma unroll
    for (int m = LPQ / 2; m >= 1; m >>= 1)
        best = min(best, __shfl_xor_sync(gmask, best, m));

    // ---- fallback: expanding rings ----
    for (int r = 2; ; ++r) {
        float bd = __uint_as_float((unsigned)(best >> 32));
        if (bd + 1e-5f < (float)(r - 1) * H) break;
        if (cx - (r - 1) <= 0 && cx + (r - 1) >= G - 1 &&
            cy - (r - 1) <= 0 && cy + (r - 1) >= G - 1) break;

        int nc = 8 * r;
        for (int tc = lane; tc < nc; tc += LPQ) {
            int i, j;
            if (tc < 2 * r + 1)      { i = cx - r + tc;               j = cy - r; }
            else if (tc < 4 * r + 2) { i = cx - r + (tc - (2*r + 1)); j = cy + r; }
            else { int s = tc - (4*r + 2); j = cy - r + 1 + (s >> 1);
                   i = (s & 1) ? cx + r : cx - r; }
            if ((unsigned)i < G && (unsigned)j < G)
                scan_cell(j * G + i, ax, ay, best);
        }
        #pragma unroll
        for (int m = LPQ / 2; m >= 1; m >>= 1)
            best = min(best, __shfl_xor_sync(gmask, best, m));
    }

    if (lane == 0) {
        int pos = (int)(best & 0xFFFFu);
        float4 pt = __ldg(&g_pts[pos]);
        ((float2*)out)[q] = make_float2(ax - pt.x, ay - pt.y);
    }
}

extern "C" void kernel_launch(void* const* d_in, const int* in_sizes, int n_in,
                              void* d_out, int out_size)
{
    const float* A = (const float*)d_in[0];   // [Q, 2]
    const float* B = (const float*)d_in[1];   // [2, N]
    float*     out = (float*)d_out;           // [Q, 2]

    const int Q = in_sizes[0] / 2;
    const int N = in_sizes[1] / 2;

    build_k<<<1, 1024>>>(B, N);

    const int total  = Q * LPQ;
    const int blocks = (total + 255) / 256;
    query_k<<<blocks, 256>>>(A, out, Q);
}